// round 9
// baseline (speedup 1.0000x reference)
#include <cuda_runtime.h>

// CrimeModelLSTM: 2-layer LSTM (H=8), B=4096, T=512, FC head [4,8].
// R9 = R8 + fix: warp A now emits the FINAL L2 partial Pa(511) in an epilogue
// before its last PAIR_BAR (R8 left slot 3 stale for B's s=511 step -> 1e-2 err).
//
// LAYER-PER-WARP decomposition. Each 64-thread pair (2 warps) owns 4 elements:
//   warp A = layer-1 engine: L1 GEMM + activations + wi2(low-k) partial of L2
//   warp B = layer-2 engine: consumes A's h1 + partial, runs L2 GEMM + acts
// One-way dependency -> ONE named bar.sync(64) per step. 4-slot smem rings.
// h stored as 2h (0.5 folded into consumer weights); sigmoid via (1+tanh)/2
// with 0.5 gate-scale folded into weights; (1+t)-form cell update.

typedef unsigned long long u64;

__device__ __forceinline__ u64 pk2(float lo, float hi) {
    u64 r; asm("mov.b64 %0, {%1,%2};" : "=l"(r) : "f"(lo), "f"(hi)); return r;
}
__device__ __forceinline__ void upk(u64 v, float& lo, float& hi) {
    asm("mov.b64 {%0,%1}, %2;" : "=f"(lo), "=f"(hi) : "l"(v));
}
__device__ __forceinline__ u64 fma2(u64 a, u64 b, u64 c) {
    u64 d; asm("fma.rn.f32x2 %0, %1, %2, %3;" : "=l"(d) : "l"(a), "l"(b), "l"(c)); return d;
}
__device__ __forceinline__ float tanhap(float x) {
    float r; asm("tanh.approx.f32 %0, %1;" : "=f"(r) : "f"(x)); return r;
}
#define PAIR_BAR(id) asm volatile("bar.sync %0, 64;" :: "r"(id) : "memory")

__global__ void __launch_bounds__(128, 4)
lstm2_kernel(const float* __restrict__ x,
             const float* __restrict__ Wih1, const float* __restrict__ Whh1,
             const float* __restrict__ bih1, const float* __restrict__ bhh1,
             const float* __restrict__ Wih2, const float* __restrict__ Whh2,
             const float* __restrict__ bih2, const float* __restrict__ bhh2,
             const float* __restrict__ Wfc,  const float* __restrict__ bfc,
             float* __restrict__ out)
{
    constexpr int T = 512;
    constexpr int H = 8;

    const int warp  = threadIdx.x >> 5;
    const int lane  = threadIdx.x & 31;
    const int pair  = warp >> 1;          // 0,1: two independent pairs per CTA
    const bool roleB = (warp & 1) != 0;   // warp-level divergence (free)
    const int grp   = lane >> 3;          // element group within warp (0..3)
    const int j     = lane & 7;           // hidden unit owned
    const int e     = (blockIdx.x * 2 + pair) * 4 + grp;
    const int barId = 1 + pair;

    // [pair][slot][grp][unit] dup-pairs; sPa: [pair][slot][grp][j] = 2 u64
    __shared__ alignas(16) u64        sh1[2][4][4][8];
    __shared__ alignas(16) u64        sh2[2][4][4][8];
    __shared__ alignas(16) ulonglong2 sPa[2][4][4][8];

    // gate scales (i,f,g,o): sigmoid rows fold 0.5; tanh row 1.0
    const float gsc[4] = {0.5f, 0.5f, 1.0f, 0.5f};

    if (!roleB) {
        // ================= Warp A: layer-1 engine =================
        u64 wx1p[2], bb1p[2], bb2p[2], wh1p[2][H], wi2lo[2][4];
        #pragma unroll
        for (int p = 0; p < 2; p++) {
            const int gA = 2 * p, gB = 2 * p + 1;
            const int rA = gA * 8 + j, rB = gB * 8 + j;
            const float sA = gsc[gA], sB = gsc[gB];
            wx1p[p] = pk2(Wih1[rA] * sA, Wih1[rB] * sB);
            bb1p[p] = pk2((bih1[rA] + bhh1[rA]) * sA, (bih1[rB] + bhh1[rB]) * sB);
            bb2p[p] = pk2((bih2[rA] + bhh2[rA]) * sA, (bih2[rB] + bhh2[rB]) * sB);
            #pragma unroll
            for (int k = 0; k < H; k++)   // h1 stored as 2*h1 -> extra 0.5
                wh1p[p][k] = pk2(Whh1[rA * H + k] * sA * 0.5f,
                                 Whh1[rB * H + k] * sB * 0.5f);
            #pragma unroll
            for (int k = 0; k < 4; k++)
                wi2lo[p][k] = pk2(Wih2[rA * H + k] * sA * 0.5f,
                                  Wih2[rB * H + k] * sB * 0.5f);
        }

        u64 h1d[H];
        #pragma unroll
        for (int k = 0; k < H; k++) h1d[k] = 0ull;
        float c1 = 0.0f;

        const float4* __restrict__ xp4 =
            reinterpret_cast<const float4*>(x + (long)e * T);
        float4 xv = xp4[0];

        for (int tt = 0; tt < T / 4; ++tt) {
            float4 xn = xp4[(tt + 1 < T / 4) ? tt + 1 : tt];
            float xs[4] = {xv.x, xv.y, xv.z, xv.w};
            #pragma unroll
            for (int q = 0; q < 4; ++q) {          // step i = 4*tt+q, i&3 == q
                u64 x2 = pk2(xs[q], xs[q]);
                u64 G0 = fma2(wx1p[0], x2, bb1p[0]);
                u64 G1 = fma2(wx1p[1], x2, bb1p[1]);
                #pragma unroll
                for (int k = 0; k < H; ++k) {
                    G0 = fma2(wh1p[0][k], h1d[k], G0);
                    G1 = fma2(wh1p[1][k], h1d[k], G1);
                }
                // L2 partial for step i-1 (uses h1(i-1) still in regs)
                u64 Pa0 = bb2p[0], Pa1 = bb2p[1];
                #pragma unroll
                for (int k = 0; k < 4; ++k) {
                    Pa0 = fma2(wi2lo[0][k], h1d[k], Pa0);
                    Pa1 = fma2(wi2lo[1][k], h1d[k], Pa1);
                }
                sPa[pair][(q + 3) & 3][grp][j] = make_ulonglong2(Pa0, Pa1);

                float a, b;
                upk(G0, a, b); const float ti = tanhap(a), tf = tanhap(b);
                upk(G1, a, b); const float tg = tanhap(a), to = tanhap(b);
                const float u = fmaf(ti, tg, tg);      // 2*sig_i*tanh_g
                const float v = fmaf(tf, c1, c1);      // 2*sig_f*c
                c1 = (u + v) * 0.5f;
                const float tc = tanhap(c1);
                const float h1o = fmaf(to, tc, tc);    // = 2*h1
                sh1[pair][q][grp][j] = pk2(h1o, h1o);

                PAIR_BAR(barId);                       // bar#i

                const ulonglong2* r =
                    reinterpret_cast<const ulonglong2*>(&sh1[pair][q][grp][0]);
                ulonglong2 r0 = r[0], r1 = r[1], r2 = r[2], r3 = r[3];
                h1d[0] = r0.x; h1d[1] = r0.y; h1d[2] = r1.x; h1d[3] = r1.y;
                h1d[4] = r2.x; h1d[5] = r2.y; h1d[6] = r3.x; h1d[7] = r3.y;
            }
            xv = xn;
        }
        // ---- epilogue (R9 fix): emit Pa(T-1) from h1(T-1) now in h1d ----
        {
            u64 Pa0 = bb2p[0], Pa1 = bb2p[1];
            #pragma unroll
            for (int k = 0; k < 4; ++k) {
                Pa0 = fma2(wi2lo[0][k], h1d[k], Pa0);
                Pa1 = fma2(wi2lo[1][k], h1d[k], Pa1);
            }
            sPa[pair][(T - 1) & 3][grp][j] = make_ulonglong2(Pa0, Pa1);
        }
        PAIR_BAR(barId);   // matches B's final iteration top bar (s = T-1)
    } else {
        // ================= Warp B: layer-2 engine =================
        u64 wi2hi[2][4], wh2p[2][H];
        #pragma unroll
        for (int p = 0; p < 2; p++) {
            const int gA = 2 * p, gB = 2 * p + 1;
            const int rA = gA * 8 + j, rB = gB * 8 + j;
            const float sA = gsc[gA], sB = gsc[gB];
            #pragma unroll
            for (int k = 0; k < 4; k++)
                wi2hi[p][k] = pk2(Wih2[rA * H + 4 + k] * sA * 0.5f,
                                  Wih2[rB * H + 4 + k] * sB * 0.5f);
            #pragma unroll
            for (int k = 0; k < H; k++)   // h2 stored as 2*h2
                wh2p[p][k] = pk2(Whh2[rA * H + k] * sA * 0.5f,
                                 Whh2[rB * H + k] * sB * 0.5f);
        }
        float c2 = 0.0f;
        float h2o = 0.0f;

        // pre-zero the h2(-1) slot (slot 3), visible after bar#0
        sh2[pair][3][grp][j] = 0ull;
        PAIR_BAR(barId);                               // bar#0

        for (int ss = 0; ss < T / 4; ++ss) {
            #pragma unroll
            for (int q = 0; q < 4; ++q) {              // step s = 4*ss+q, s&3==q
                PAIR_BAR(barId);                       // bar#(s+1)

                const ulonglong2 pa = sPa[pair][q][grp][j];
                const ulonglong2* rh1 =
                    reinterpret_cast<const ulonglong2*>(&sh1[pair][q][grp][4]);
                const ulonglong2 a0 = rh1[0], a1 = rh1[1];
                const ulonglong2* rh2 =
                    reinterpret_cast<const ulonglong2*>(&sh2[pair][(q + 3) & 3][grp][0]);
                const ulonglong2 b0 = rh2[0], b1 = rh2[1], b2 = rh2[2], b3 = rh2[3];

                u64 P0 = pa.x, P1 = pa.y;
                const u64 h1hi[4] = {a0.x, a0.y, a1.x, a1.y};
                const u64 h2d[8]  = {b0.x, b0.y, b1.x, b1.y,
                                     b2.x, b2.y, b3.x, b3.y};
                #pragma unroll
                for (int k = 0; k < 4; ++k) {
                    P0 = fma2(wi2hi[0][k], h1hi[k], P0);
                    P1 = fma2(wi2hi[1][k], h1hi[k], P1);
                }
                #pragma unroll
                for (int k = 0; k < H; ++k) {
                    P0 = fma2(wh2p[0][k], h2d[k], P0);
                    P1 = fma2(wh2p[1][k], h2d[k], P1);
                }

                float a, b;
                upk(P0, a, b); const float ti = tanhap(a), tf = tanhap(b);
                upk(P1, a, b); const float tg = tanhap(a), to = tanhap(b);
                const float u = fmaf(ti, tg, tg);
                const float v = fmaf(tf, c2, c2);
                c2 = (u + v) * 0.5f;
                const float tc = tanhap(c2);
                h2o = fmaf(to, tc, tc);                // = 2*h2
                sh2[pair][q][grp][j] = pk2(h2o, h2o);
            }
        }

        // ---- FC head: h2o (=2*h2(T-1)) lives on lane grp*8+k for unit k ----
        const int base = lane & 24;
        float hv[H];
        #pragma unroll
        for (int k = 0; k < H; k++)
            hv[k] = __shfl_sync(0xffffffffu, h2o, base + k);
        if (j < 4) {
            float acc = bfc[j];
            #pragma unroll
            for (int k = 0; k < H; k++)
                acc = fmaf(Wfc[j * H + k] * 0.5f, hv[k], acc);
            out[e * 4 + j] = acc;
        }
    }
}

extern "C" void kernel_launch(void* const* d_in, const int* in_sizes, int n_in,
                              void* d_out, int out_size)
{
    const float* x    = (const float*)d_in[0];
    const float* Wih1 = (const float*)d_in[1];
    const float* Whh1 = (const float*)d_in[2];
    const float* bih1 = (const float*)d_in[3];
    const float* bhh1 = (const float*)d_in[4];
    const float* Wih2 = (const float*)d_in[5];
    const float* Whh2 = (const float*)d_in[6];
    const float* bih2 = (const float*)d_in[7];
    const float* bhh2 = (const float*)d_in[8];
    const float* Wfc  = (const float*)d_in[9];
    const float* bfc  = (const float*)d_in[10];
    float* out = (float*)d_out;

    const int B = 4096;
    // 8 elements per CTA (2 pairs x 4) -> 512 CTAs, 2048 warps
    dim3 grid(B / 8), block(128);
    lstm2_kernel<<<grid, block>>>(x, Wih1, Whh1, bih1, bhh1,
                                  Wih2, Whh2, bih2, bhh2, Wfc, bfc, out);
}